// round 1
// baseline (speedup 1.0000x reference)
#include <cuda_runtime.h>

#define N_NODES 50000
#define N_EDGES 800000
#define D_FEAT  128

// CSR row pointer scratch (device global: no runtime allocation allowed).
__device__ int g_row_ptr[N_NODES + 1];

// Edge-parallel CSR construction from sorted COO rows.
// Thread e fills row_ptr[q] = e for all q in (rows[e-1], rows[e]].
__global__ void build_row_ptr_kernel(const int* __restrict__ rows,
                                     int n_edges, int n_nodes) {
    int e = blockIdx.x * blockDim.x + threadIdx.x;
    if (e >= n_edges) return;
    int r = rows[e];
    int rprev = (e == 0) ? -1 : rows[e - 1];
    for (int q = rprev + 1; q <= r; q++) g_row_ptr[q] = e;
    if (e == n_edges - 1) {
        for (int q = r + 1; q <= n_nodes; q++) g_row_ptr[q] = n_edges;
    }
}

// One warp per row. Lane l owns features [4l, 4l+4) as a float4.
// Atomic-free: each row's segment is contiguous (rows sorted), accumulate in
// registers, one plain STG.128 per lane at the end. Empty rows store zeros,
// which also initializes the poisoned output buffer.
__global__ __launch_bounds__(256)
void spmm_coo_kernel(const float* __restrict__ x,
                     const float* __restrict__ vals,
                     const int* __restrict__ cols,
                     float* __restrict__ out) {
    int warp = (blockIdx.x * blockDim.x + threadIdx.x) >> 5;
    int lane = threadIdx.x & 31;
    if (warp >= N_NODES) return;

    int start = g_row_ptr[warp];
    int end   = g_row_ptr[warp + 1];

    const float4* __restrict__ x4 = (const float4*)x;
    float4 acc = make_float4(0.f, 0.f, 0.f, 0.f);

    for (int base = start; base < end; base += 32) {
        int n = end - base;
        if (n > 32) n = 32;

        // Cooperative, coalesced load of this chunk's edge metadata.
        int   c = 0;
        float v = 0.f;
        if (lane < n) {
            c = cols[base + lane];
            v = vals[base + lane];
        }

        // Broadcast each edge; gathers are independent of acc -> MLP.
        #pragma unroll 4
        for (int j = 0; j < n; j++) {
            int   cj = __shfl_sync(0xffffffffu, c, j);
            float vj = __shfl_sync(0xffffffffu, v, j);
            float4 xv = x4[(size_t)cj * (D_FEAT / 4) + lane];
            acc.x += vj * xv.x;
            acc.y += vj * xv.y;
            acc.z += vj * xv.z;
            acc.w += vj * xv.w;
        }
    }

    ((float4*)out)[(size_t)warp * (D_FEAT / 4) + lane] = acc;
}

extern "C" void kernel_launch(void* const* d_in, const int* in_sizes, int n_in,
                              void* d_out, int out_size) {
    const float* x    = (const float*)d_in[0];
    const float* vals = (const float*)d_in[1];
    const int*   rows = (const int*)d_in[2];
    const int*   cols = (const int*)d_in[3];
    float*       out  = (float*)d_out;

    (void)in_sizes; (void)n_in; (void)out_size;

    // 1) CSR row_ptr from sorted COO rows.
    {
        int threads = 256;
        int blocks  = (N_EDGES + threads - 1) / threads;
        build_row_ptr_kernel<<<blocks, threads>>>(rows, N_EDGES, N_NODES);
    }

    // 2) Warp-per-row SpMM, atomic-free.
    {
        int threads = 256;                       // 8 warps per block
        int warps_needed = N_NODES;
        int blocks = (warps_needed * 32 + threads - 1) / threads;
        spmm_coo_kernel<<<blocks, threads>>>(x, vals, cols, out);
    }
}